// round 2
// baseline (speedup 1.0000x reference)
#include <cuda_runtime.h>
#include <math.h>

// Problem constants
#define BB   32
#define IDF  1024
#define CDF  1024
#define QQ   2304     // 48*48
#define SS   256

// Scratch (device globals: allocation-free per harness rules)
__device__ float g_sourceT[(size_t)BB * IDF * SS];   // [B, IDF, S]   33.5 MB
__device__ float g_attn   [(size_t)BB * QQ  * SS];   // [B, Q, S]     75.5 MB

// ---------------------------------------------------------------------------
// SGEMM NN: C[M,N] = A[M,K] * B[K,N], all row-major. Dims must be multiples
// of (128,128,8). Batched via blockIdx.z with 64-bit strides.
// ---------------------------------------------------------------------------
__global__ __launch_bounds__(256)
void sgemm_nn(const float* __restrict__ A, const float* __restrict__ Bm,
              float* __restrict__ C, int M, int N, int K,
              long long sA, long long sB, long long sC) {
    const int BM = 128, BN = 128, BK = 8, TM = 8, TN = 8;
    A  += (long long)blockIdx.z * sA;
    Bm += (long long)blockIdx.z * sB;
    C  += (long long)blockIdx.z * sC;

    const int cRow = blockIdx.y, cCol = blockIdx.x;
    __shared__ float As[BK][BM];
    __shared__ float Bs[BK][BN];
    const int tid = threadIdx.x;

    const int aRow = tid >> 1;            // 0..127
    const int aCol = (tid & 1) * 4;       // 0 or 4
    const int bRow = tid >> 5;            // 0..7
    const int bCol = (tid & 31) * 4;      // 0..124

    A  += (long long)cRow * BM * K;
    Bm += cCol * BN;
    C  += (long long)cRow * BM * N + cCol * BN;

    float acc[TM][TN] = {};
    float rM[TM], rN[TN];
    const int tRow = (tid >> 4) * TM;
    const int tCol = (tid & 15) * TN;

    for (int k0 = 0; k0 < K; k0 += BK) {
        float4 a4 = *(const float4*)(A + (long long)aRow * K + aCol);
        As[aCol + 0][aRow] = a4.x;
        As[aCol + 1][aRow] = a4.y;
        As[aCol + 2][aRow] = a4.z;
        As[aCol + 3][aRow] = a4.w;
        *(float4*)(&Bs[bRow][bCol]) = *(const float4*)(Bm + (long long)bRow * N + bCol);
        __syncthreads();
        A += BK;  Bm += (long long)BK * N;
#pragma unroll
        for (int k = 0; k < BK; k++) {
#pragma unroll
            for (int i = 0; i < TM; i++) rM[i] = As[k][tRow + i];
#pragma unroll
            for (int j = 0; j < TN; j++) rN[j] = Bs[k][tCol + j];
#pragma unroll
            for (int i = 0; i < TM; i++)
#pragma unroll
                for (int j = 0; j < TN; j++) acc[i][j] += rM[i] * rN[j];
        }
        __syncthreads();
    }
#pragma unroll
    for (int i = 0; i < TM; i++)
#pragma unroll
        for (int j = 0; j < TN; j += 4) {
            float4 v = make_float4(acc[i][j], acc[i][j+1], acc[i][j+2], acc[i][j+3]);
            *(float4*)(&C[(long long)(tRow + i) * N + tCol + j]) = v;
        }
}

// ---------------------------------------------------------------------------
// SGEMM TN: C[M,N] = A^T * B, A stored [K,M] row-major, B [K,N] row-major.
// ---------------------------------------------------------------------------
__global__ __launch_bounds__(256)
void sgemm_tn(const float* __restrict__ A, const float* __restrict__ Bm,
              float* __restrict__ C, int M, int N, int K,
              long long sA, long long sB, long long sC) {
    const int BM = 128, BN = 128, BK = 8, TM = 8, TN = 8;
    A  += (long long)blockIdx.z * sA;
    Bm += (long long)blockIdx.z * sB;
    C  += (long long)blockIdx.z * sC;

    const int cRow = blockIdx.y, cCol = blockIdx.x;
    __shared__ float As[BK][BM];
    __shared__ float Bs[BK][BN];
    const int tid = threadIdx.x;

    const int aRow = tid >> 5;            // k row 0..7
    const int aCol = (tid & 31) * 4;      // m col 0..124
    const int bRow = tid >> 5;
    const int bCol = (tid & 31) * 4;

    A  += cRow * BM;                       // column offset into [K, M] (lda = M)
    Bm += cCol * BN;
    C  += (long long)cRow * BM * N + cCol * BN;

    float acc[TM][TN] = {};
    float rM[TM], rN[TN];
    const int tRow = (tid >> 4) * TM;
    const int tCol = (tid & 15) * TN;

    for (int k0 = 0; k0 < K; k0 += BK) {
        *(float4*)(&As[aRow][aCol]) = *(const float4*)(A + (long long)aRow * M + aCol);
        *(float4*)(&Bs[bRow][bCol]) = *(const float4*)(Bm + (long long)bRow * N + bCol);
        __syncthreads();
        A  += (long long)BK * M;
        Bm += (long long)BK * N;
#pragma unroll
        for (int k = 0; k < BK; k++) {
#pragma unroll
            for (int i = 0; i < TM; i++) rM[i] = As[k][tRow + i];
#pragma unroll
            for (int j = 0; j < TN; j++) rN[j] = Bs[k][tCol + j];
#pragma unroll
            for (int i = 0; i < TM; i++)
#pragma unroll
                for (int j = 0; j < TN; j++) acc[i][j] += rM[i] * rN[j];
        }
        __syncthreads();
    }
#pragma unroll
    for (int i = 0; i < TM; i++)
#pragma unroll
        for (int j = 0; j < TN; j += 4) {
            float4 v = make_float4(acc[i][j], acc[i][j+1], acc[i][j+2], acc[i][j+3]);
            *(float4*)(&C[(long long)(tRow + i) * N + tCol + j]) = v;
        }
}

// ---------------------------------------------------------------------------
// SGEMM NT: C[M,N] = A * B^T, A [M,K] row-major, B stored [N,K] row-major.
// ---------------------------------------------------------------------------
__global__ __launch_bounds__(256)
void sgemm_nt(const float* __restrict__ A, const float* __restrict__ Bm,
              float* __restrict__ C, int M, int N, int K,
              long long sA, long long sB, long long sC) {
    const int BM = 128, BN = 128, BK = 8, TM = 8, TN = 8;
    A  += (long long)blockIdx.z * sA;
    Bm += (long long)blockIdx.z * sB;
    C  += (long long)blockIdx.z * sC;

    const int cRow = blockIdx.y, cCol = blockIdx.x;
    __shared__ float As[BK][BM];
    __shared__ float Bs[BK][BN];
    const int tid = threadIdx.x;

    const int aRow = tid >> 1;            // m 0..127
    const int aCol = (tid & 1) * 4;       // k 0 or 4
    const int bRow = tid >> 1;            // n 0..127
    const int bCol = (tid & 1) * 4;       // k 0 or 4

    A  += (long long)cRow * BM * K;
    Bm += (long long)cCol * BN * K;
    C  += (long long)cRow * BM * N + cCol * BN;

    float acc[TM][TN] = {};
    float rM[TM], rN[TN];
    const int tRow = (tid >> 4) * TM;
    const int tCol = (tid & 15) * TN;

    for (int k0 = 0; k0 < K; k0 += BK) {
        float4 a4 = *(const float4*)(A + (long long)aRow * K + aCol);
        As[aCol + 0][aRow] = a4.x;
        As[aCol + 1][aRow] = a4.y;
        As[aCol + 2][aRow] = a4.z;
        As[aCol + 3][aRow] = a4.w;
        float4 b4 = *(const float4*)(Bm + (long long)bRow * K + bCol);
        Bs[bCol + 0][bRow] = b4.x;
        Bs[bCol + 1][bRow] = b4.y;
        Bs[bCol + 2][bRow] = b4.z;
        Bs[bCol + 3][bRow] = b4.w;
        __syncthreads();
        A  += BK;
        Bm += BK;
#pragma unroll
        for (int k = 0; k < BK; k++) {
#pragma unroll
            for (int i = 0; i < TM; i++) rM[i] = As[k][tRow + i];
#pragma unroll
            for (int j = 0; j < TN; j++) rN[j] = Bs[k][tCol + j];
#pragma unroll
            for (int i = 0; i < TM; i++)
#pragma unroll
                for (int j = 0; j < TN; j++) acc[i][j] += rM[i] * rN[j];
        }
        __syncthreads();
    }
#pragma unroll
    for (int i = 0; i < TM; i++)
#pragma unroll
        for (int j = 0; j < TN; j += 4) {
            float4 v = make_float4(acc[i][j], acc[i][j+1], acc[i][j+2], acc[i][j+3]);
            *(float4*)(&C[(long long)(tRow + i) * N + tCol + j]) = v;
        }
}

// ---------------------------------------------------------------------------
// Masked softmax over S=256. One block per row of attn [B*Q, S].
// Faithful-to-reference mask tiling: row (b*Q + q) uses mask[(b*Q+q) % B];
// since Q % B == 0 this is mask[q % 32].
//
// Mask dtype robustness: the harness converts bool inputs to a 4-byte dtype
// (int32 or float32). For BOTH encodings, "masked" == nonzero 32-bit word
// (int 1 / float 1.0f are nonzero; 0 is all-zero bits in both).
// ---------------------------------------------------------------------------
__global__ void softmax_mask_kernel(float* __restrict__ attn,
                                    const unsigned int* __restrict__ mask) {
    const long long row = blockIdx.x;
    const int q = (int)(row % QQ);
    const int s = threadIdx.x;

    float v = attn[row * SS + s];
    if (mask[(q & (BB - 1)) * SS + s] != 0u) v = -1e30f;   // masked -> -inf

    // block max (256 threads = 8 warps)
    __shared__ float red[8];
    float m = v;
#pragma unroll
    for (int o = 16; o > 0; o >>= 1) m = fmaxf(m, __shfl_xor_sync(0xffffffffu, m, o));
    if ((s & 31) == 0) red[s >> 5] = m;
    __syncthreads();
    float mx = red[0];
#pragma unroll
    for (int i = 1; i < 8; i++) mx = fmaxf(mx, red[i]);
    __syncthreads();

    float e = __expf(v - mx);

    float t = e;
#pragma unroll
    for (int o = 16; o > 0; o >>= 1) t += __shfl_xor_sync(0xffffffffu, t, o);
    if ((s & 31) == 0) red[s >> 5] = t;
    __syncthreads();
    float sum = 0.f;
#pragma unroll
    for (int i = 0; i < 8; i++) sum += red[i];

    attn[row * SS + s] = e / sum;
}

// ---------------------------------------------------------------------------
// Transpose per-batch [Q, S] -> [S, Q] into the attn_out region of d_out.
// ---------------------------------------------------------------------------
__global__ void transpose_qs_kernel(const float* __restrict__ attn,
                                    float* __restrict__ out) {
    __shared__ float tile[32][33];
    const int b  = blockIdx.z;
    const int s0 = blockIdx.x * 32;
    const int q0 = blockIdx.y * 32;
    const float* src = attn + (long long)b * QQ * SS;
    float*       dst = out  + (long long)b * SS * QQ;
    const int x = threadIdx.x, y = threadIdx.y;   // (32, 8)
#pragma unroll
    for (int i = 0; i < 32; i += 8)
        tile[y + i][x] = src[(long long)(q0 + y + i) * SS + s0 + x];
    __syncthreads();
#pragma unroll
    for (int i = 0; i < 32; i += 8)
        dst[(long long)(s0 + y + i) * QQ + q0 + x] = tile[x][y + i];
}

// ---------------------------------------------------------------------------
// Launch
// ---------------------------------------------------------------------------
extern "C" void kernel_launch(void* const* d_in, const int* in_sizes, int n_in,
                              void* d_out, int out_size) {
    const float*        input   = (const float*)d_in[0];          // [B, IDF, 48, 48]
    const float*        context = (const float*)d_in[1];          // [B, CDF, S]
    const unsigned int* mask    = (const unsigned int*)d_in[2];   // [B, S] bool as 4-byte
    const float*        W       = (const float*)d_in[3];          // [IDF, CDF]

    float* out      = (float*)d_out;
    float* wc       = out;                                   // [B, IDF, Q]
    float* attn_out = out + (size_t)BB * IDF * QQ;           // [B, S, Q]

    float* sourceT;  cudaGetSymbolAddress((void**)&sourceT, g_sourceT);
    float* attn;     cudaGetSymbolAddress((void**)&attn,    g_attn);

    // 1) sourceT[b] = W[IDF,CDF] * context[b][CDF,S]
    sgemm_nn<<<dim3(SS / 128, IDF / 128, BB), 256>>>(
        W, context, sourceT, IDF, SS, CDF,
        0LL, (long long)CDF * SS, (long long)IDF * SS);

    // 2) attn[b] = input[b]^T (IDFxQ stored [K,M]) * sourceT[b]  -> [Q, S]
    sgemm_tn<<<dim3(SS / 128, QQ / 128, BB), 256>>>(
        input, sourceT, attn, QQ, SS, IDF,
        (long long)IDF * QQ, (long long)IDF * SS, (long long)QQ * SS);

    // 3) masked softmax over S (in place)
    softmax_mask_kernel<<<BB * QQ, SS>>>(attn, mask);

    // 4) attn_out[b] = attn[b]^T  -> [S, Q]
    transpose_qs_kernel<<<dim3(SS / 32, QQ / 32, BB), dim3(32, 8)>>>(attn, attn_out);

    // 5) wc[b] = sourceT[b][IDF,S] * attn[b]^T ([Q,S] stored [N,K]) -> [IDF, Q]
    sgemm_nt<<<dim3(QQ / 128, IDF / 128, BB), 256>>>(
        sourceT, attn, wc, IDF, QQ, SS,
        (long long)IDF * SS, (long long)QQ * SS, (long long)IDF * QQ);
}

// round 9
// speedup vs baseline: 2.0110x; 2.0110x over previous
#include <cuda_runtime.h>
#include <cuda_bf16.h>
#include <math.h>
#include <stdint.h>

// Problem constants
#define BB   32
#define IDF  1024
#define CDF  1024
#define QQ   2304     // 48*48
#define SS   256

// ---------------------------------------------------------------------------
// Device-global scratch (allocation-free per harness rules)
// ---------------------------------------------------------------------------
__device__ float g_sourceT[(size_t)BB * IDF * SS];                 // [B, IDF, S]
__device__ float g_attn   [(size_t)BB * QQ  * SS];                 // [B, Q, S]

__device__ __align__(16) __nv_bfloat16 g_Whi  [(size_t)IDF * CDF];
__device__ __align__(16) __nv_bfloat16 g_Wlo  [(size_t)IDF * CDF];
__device__ __align__(16) __nv_bfloat16 g_ctxThi[(size_t)BB * SS * CDF];   // [B][S, CDF]
__device__ __align__(16) __nv_bfloat16 g_ctxTlo[(size_t)BB * SS * CDF];
__device__ __align__(16) __nv_bfloat16 g_inThi [(size_t)BB * QQ * IDF];   // [B][Q, IDF]
__device__ __align__(16) __nv_bfloat16 g_inTlo [(size_t)BB * QQ * IDF];
__device__ __align__(16) __nv_bfloat16 g_sThi  [(size_t)BB * IDF * SS];   // [B][IDF, S]
__device__ __align__(16) __nv_bfloat16 g_sTlo  [(size_t)BB * IDF * SS];
__device__ __align__(16) __nv_bfloat16 g_sTThi [(size_t)BB * SS * IDF];   // [B][S, IDF]
__device__ __align__(16) __nv_bfloat16 g_sTTlo [(size_t)BB * SS * IDF];
__device__ __align__(16) __nv_bfloat16 g_attnhi[(size_t)BB * QQ * SS];    // [B][Q, S]
__device__ __align__(16) __nv_bfloat16 g_attnlo[(size_t)BB * QQ * SS];

// ---------------------------------------------------------------------------
// Helpers (plain sm_80-class instructions only: legal on target sm_103)
// ---------------------------------------------------------------------------
__device__ __forceinline__ uint32_t smem_u32(const void* p) {
    uint32_t a;
    asm("{ .reg .u64 t; cvta.to.shared.u64 t, %1; cvt.u32.u64 %0, t; }" : "=r"(a) : "l"(p));
    return a;
}
__device__ __forceinline__ void cp16(uint32_t s, const void* g) {
    asm volatile("cp.async.cg.shared.global [%0], [%1], 16;" :: "r"(s), "l"(g));
}
#define CP_COMMIT() asm volatile("cp.async.commit_group;" ::: "memory")
#define CP_WAIT(n)  asm volatile("cp.async.wait_group %0;" :: "n"(n) : "memory")

#define LDSM4(r, a) \
    asm volatile("ldmatrix.sync.aligned.m8n8.x4.shared.b16 {%0,%1,%2,%3}, [%4];" \
        : "=r"((r)[0]), "=r"((r)[1]), "=r"((r)[2]), "=r"((r)[3]) : "r"(a))

#define MMA_BF16(d, a, b0, b1) \
    asm volatile("mma.sync.aligned.m16n8k16.row.col.f32.bf16.bf16.f32 " \
        "{%0,%1,%2,%3}, {%4,%5,%6,%7}, {%8,%9}, {%0,%1,%2,%3};" \
        : "+f"((d)[0]), "+f"((d)[1]), "+f"((d)[2]), "+f"((d)[3]) \
        : "r"((a)[0]), "r"((a)[1]), "r"((a)[2]), "r"((a)[3]), "r"(b0), "r"(b1))

// ---------------------------------------------------------------------------
// bf16x3 split-precision batched GEMM (HMMA): D[m,n] = sum_k A[m,k]*B[n,k]
// A = Ahi+Alo [M,K] K-major, B = Bhi+Blo [N,K] K-major.
// Tile 128x128xBK32, 256 thr (8 warps, 4m x 2n), warp tile 32x64.
// Smem: 4 planes x 128 rows x 80B (64B data + 16B pad; row*80 mod 128 covers
// all eight 16B slots -> conflict-free ldmatrix), double buffered = 80 KB.
// ---------------------------------------------------------------------------
#define PLANE_SZ 10240            // 128 * 80
#define STAGE_SZ 40960            // 4 planes
#define GEMM_SMEM (2 * STAGE_SZ)  // 81920

__global__ __launch_bounds__(256, 1)
void gemm_bf16x3(const __nv_bfloat16* __restrict__ Ahi, const __nv_bfloat16* __restrict__ Alo,
                 const __nv_bfloat16* __restrict__ Bhi, const __nv_bfloat16* __restrict__ Blo,
                 float* __restrict__ C, int K,
                 long long sA, long long sB, long long sC, int Ncols) {
    extern __shared__ __align__(128) char smem[];
    const uint32_t sbase = smem_u32(smem);
    const int tid = threadIdx.x, wid = tid >> 5, lane = tid & 31;
    const int m0 = blockIdx.y * 128;
    const int n0 = blockIdx.x * 128;
    const long long bz = blockIdx.z;
    Ahi += bz * sA; Alo += bz * sA;
    Bhi += bz * sB; Blo += bz * sB;
    C   += bz * sC;

    const __nv_bfloat16* pl[4] = {Ahi, Alo, Bhi, Blo};

    // Stage loader: 2048 16B chunks (4 planes x 128 rows x 4), 8 per thread.
    auto load_stage = [&](int kt, int st) {
        const uint32_t s0 = sbase + st * STAGE_SZ;
        const int k0 = kt * 32;
#pragma unroll
        for (int i = 0; i < 8; i++) {
            int ch = i * 256 + tid;
            int p  = ch >> 9;           // plane 0..3
            int rc = ch & 511;
            int r  = rc >> 2, c = rc & 3;
            int row = (p < 2 ? m0 : n0) + r;
            cp16(s0 + p * PLANE_SZ + r * 80 + c * 16,
                 pl[p] + (long long)row * K + k0 + c * 8);
        }
        CP_COMMIT();
    };

    const int wm = (wid & 3) * 32;   // warp m offset in tile
    const int wn = (wid >> 2) * 64;  // warp n offset in tile

    float acc[2][8][4];
#pragma unroll
    for (int mt = 0; mt < 2; mt++)
#pragma unroll
        for (int nt = 0; nt < 8; nt++)
#pragma unroll
            for (int e = 0; e < 4; e++) acc[mt][nt][e] = 0.f;

    const int KT = K / 32;
    load_stage(0, 0);

    for (int t = 0; t < KT; t++) {
        if (t + 1 < KT) { load_stage(t + 1, (t + 1) & 1); CP_WAIT(1); }
        else            { CP_WAIT(0); }
        __syncthreads();

        const uint32_t s0 = sbase + (t & 1) * STAGE_SZ;
#pragma unroll
        for (int ks = 0; ks < 2; ks++) {
            const uint32_t kb = ks * 32;  // k16 half in bytes
            // A fragments: lanes 0-15 -> rows @k0, 16-31 -> rows @k8
            uint32_t ah[2][4], al[2][4];
#pragma unroll
            for (int mt = 0; mt < 2; mt++) {
                uint32_t aaddr = s0 + (wm + mt * 16 + (lane & 15)) * 80 + kb + (lane >> 4) * 16;
                LDSM4(ah[mt], aaddr);
                LDSM4(al[mt], aaddr + PLANE_SZ);
            }
            // B fragments per n16 group: lanes 0-7 n0-7@k0, 8-15 n0-7@k8,
            // 16-23 n8-15@k0, 24-31 n8-15@k8
#pragma unroll
            for (int ng = 0; ng < 4; ng++) {
                uint32_t bh[4], bl[4];
                uint32_t baddr = s0 + 2 * PLANE_SZ
                               + (wn + ng * 16 + (lane & 7) + (lane >> 4) * 8) * 80
                               + kb + ((lane >> 3) & 1) * 16;
                LDSM4(bh, baddr);
                LDSM4(bl, baddr + PLANE_SZ);
#pragma unroll
                for (int mt = 0; mt < 2; mt++) {
                    MMA_BF16(acc[mt][ng * 2],     ah[mt], bh[0], bh[1]);   // hi*hi
                    MMA_BF16(acc[mt][ng * 2],     ah[mt], bl[0], bl[1]);   // hi*lo
                    MMA_BF16(acc[mt][ng * 2],     al[mt], bh[0], bh[1]);   // lo*hi
                    MMA_BF16(acc[mt][ng * 2 + 1], ah[mt], bh[2], bh[3]);
                    MMA_BF16(acc[mt][ng * 2 + 1], ah[mt], bl[2], bl[3]);
                    MMA_BF16(acc[mt][ng * 2 + 1], al[mt], bh[2], bh[3]);
                }
            }
        }
        __syncthreads();
    }

    // Epilogue: fragment layout c0,c1 -> (g, 2j..2j+1); c2,c3 -> (g+8, ...)
    const int g = lane >> 2, j2 = (lane & 3) * 2;
#pragma unroll
    for (int mt = 0; mt < 2; mt++)
#pragma unroll
        for (int nt = 0; nt < 8; nt++) {
            long long row = m0 + wm + mt * 16 + g;
            long long col = n0 + wn + nt * 8 + j2;
            *(float2*)&C[row * Ncols + col]       = make_float2(acc[mt][nt][0], acc[mt][nt][1]);
            *(float2*)&C[(row + 8) * Ncols + col] = make_float2(acc[mt][nt][2], acc[mt][nt][3]);
        }
}

// ---------------------------------------------------------------------------
// Elementwise hi/lo split (flat, float4-vectorized)
// ---------------------------------------------------------------------------
__global__ void split_kernel(const float* __restrict__ src,
                             __nv_bfloat16* __restrict__ hi,
                             __nv_bfloat16* __restrict__ lo, long long n4) {
    long long i = (long long)blockIdx.x * blockDim.x + threadIdx.x;
    if (i >= n4) return;
    float4 v = ((const float4*)src)[i];
    float a[4] = {v.x, v.y, v.z, v.w};
    __nv_bfloat16 h[4], l[4];
#pragma unroll
    for (int k = 0; k < 4; k++) {
        h[k] = __float2bfloat16(a[k]);
        l[k] = __float2bfloat16(a[k] - __bfloat162float(h[k]));
    }
    ((__nv_bfloat162*)hi)[2 * i]     = __nv_bfloat162(h[0], h[1]);
    ((__nv_bfloat162*)hi)[2 * i + 1] = __nv_bfloat162(h[2], h[3]);
    ((__nv_bfloat162*)lo)[2 * i]     = __nv_bfloat162(l[0], l[1]);
    ((__nv_bfloat162*)lo)[2 * i + 1] = __nv_bfloat162(l[2], l[3]);
}

// ---------------------------------------------------------------------------
// Split + transpose: src [b][R,C] fp32 -> hiT/loT [b][C,R] bf16
// grid (C/32, R/32, B), block (32, 8)
// ---------------------------------------------------------------------------
__global__ void split_transpose_kernel(const float* __restrict__ src,
                                       __nv_bfloat16* __restrict__ hiT,
                                       __nv_bfloat16* __restrict__ loT,
                                       int R, int C) {
    __shared__ float tile[32][33];
    const long long base = (long long)blockIdx.z * R * C;
    const int c0 = blockIdx.x * 32, r0 = blockIdx.y * 32;
    const int x = threadIdx.x, y = threadIdx.y;
    const float* s = src + base;
#pragma unroll
    for (int i = 0; i < 32; i += 8)
        tile[y + i][x] = s[(long long)(r0 + y + i) * C + c0 + x];
    __syncthreads();
#pragma unroll
    for (int i = 0; i < 32; i += 8) {
        float v = tile[x][y + i];
        __nv_bfloat16 h = __float2bfloat16(v);
        long long o = base + (long long)(c0 + y + i) * R + r0 + x;
        hiT[o] = h;
        loT[o] = __float2bfloat16(v - __bfloat162float(h));
    }
}

// ---------------------------------------------------------------------------
// Masked softmax over S=256 (in place) + emit hi/lo bf16 planes.
// Row (b*Q+q) uses mask[q % 32] (faithful to reference tiling; Q % B == 0).
// Mask: harness 4-byte encoding; nonzero word == masked (int32 or fp32).
// ---------------------------------------------------------------------------
__global__ void softmax_mask_kernel(float* __restrict__ attn,
                                    const unsigned int* __restrict__ mask,
                                    __nv_bfloat16* __restrict__ ahi,
                                    __nv_bfloat16* __restrict__ alo) {
    const long long row = blockIdx.x;
    const int q = (int)(row % QQ);
    const int s = threadIdx.x;

    float v = attn[row * SS + s];
    if (mask[(q & (BB - 1)) * SS + s] != 0u) v = -1e30f;

    __shared__ float red[8];
    float m = v;
#pragma unroll
    for (int o = 16; o > 0; o >>= 1) m = fmaxf(m, __shfl_xor_sync(0xffffffffu, m, o));
    if ((s & 31) == 0) red[s >> 5] = m;
    __syncthreads();
    float mx = red[0];
#pragma unroll
    for (int i = 1; i < 8; i++) mx = fmaxf(mx, red[i]);
    __syncthreads();

    float e = __expf(v - mx);
    float t = e;
#pragma unroll
    for (int o = 16; o > 0; o >>= 1) t += __shfl_xor_sync(0xffffffffu, t, o);
    if ((s & 31) == 0) red[s >> 5] = t;
    __syncthreads();
    float sum = 0.f;
#pragma unroll
    for (int i = 0; i < 8; i++) sum += red[i];

    float p = e / sum;
    attn[row * SS + s] = p;
    __nv_bfloat16 h = __float2bfloat16(p);
    ahi[row * SS + s] = h;
    alo[row * SS + s] = __float2bfloat16(p - __bfloat162float(h));
}

// ---------------------------------------------------------------------------
// Transpose per-batch [Q, S] -> [S, Q] into attn_out
// ---------------------------------------------------------------------------
__global__ void transpose_qs_kernel(const float* __restrict__ attn,
                                    float* __restrict__ out) {
    __shared__ float tile[32][33];
    const int b  = blockIdx.z;
    const int s0 = blockIdx.x * 32;
    const int q0 = blockIdx.y * 32;
    const float* src = attn + (long long)b * QQ * SS;
    float*       dst = out  + (long long)b * SS * QQ;
    const int x = threadIdx.x, y = threadIdx.y;
#pragma unroll
    for (int i = 0; i < 32; i += 8)
        tile[y + i][x] = src[(long long)(q0 + y + i) * SS + s0 + x];
    __syncthreads();
#pragma unroll
    for (int i = 0; i < 32; i += 8)
        dst[(long long)(s0 + y + i) * QQ + q0 + x] = tile[x][y + i];
}

// ---------------------------------------------------------------------------
// Launch
// ---------------------------------------------------------------------------
extern "C" void kernel_launch(void* const* d_in, const int* in_sizes, int n_in,
                              void* d_out, int out_size) {
    const float*        input   = (const float*)d_in[0];          // [B, IDF, 48, 48]
    const float*        context = (const float*)d_in[1];          // [B, CDF, S]
    const unsigned int* mask    = (const unsigned int*)d_in[2];   // [B, S]
    const float*        W       = (const float*)d_in[3];          // [IDF, CDF]

    float* out      = (float*)d_out;
    float* wc       = out;                                  // [B, IDF, Q]
    float* attn_out = out + (size_t)BB * IDF * QQ;          // [B, S, Q]

    float *sourceT, *attn;
    __nv_bfloat16 *Whi, *Wlo, *ctxThi, *ctxTlo, *inThi, *inTlo;
    __nv_bfloat16 *sThi, *sTlo, *sTThi, *sTTlo, *athi, *atlo;
    cudaGetSymbolAddress((void**)&sourceT, g_sourceT);
    cudaGetSymbolAddress((void**)&attn,    g_attn);
    cudaGetSymbolAddress((void**)&Whi,     g_Whi);
    cudaGetSymbolAddress((void**)&Wlo,     g_Wlo);
    cudaGetSymbolAddress((void**)&ctxThi,  g_ctxThi);
    cudaGetSymbolAddress((void**)&ctxTlo,  g_ctxTlo);
    cudaGetSymbolAddress((void**)&inThi,   g_inThi);
    cudaGetSymbolAddress((void**)&inTlo,   g_inTlo);
    cudaGetSymbolAddress((void**)&sThi,    g_sThi);
    cudaGetSymbolAddress((void**)&sTlo,    g_sTlo);
    cudaGetSymbolAddress((void**)&sTThi,   g_sTThi);
    cudaGetSymbolAddress((void**)&sTTlo,   g_sTTlo);
    cudaGetSymbolAddress((void**)&athi,    g_attnhi);
    cudaGetSymbolAddress((void**)&atlo,    g_attnlo);

    cudaFuncSetAttribute(gemm_bf16x3, cudaFuncAttributeMaxDynamicSharedMemorySize, GEMM_SMEM);

    // Stage bf16 hi/lo planes
    split_kernel<<<(IDF * CDF / 4 + 255) / 256, 256>>>(W, Whi, Wlo, (long long)IDF * CDF / 4);
    split_transpose_kernel<<<dim3(SS / 32, CDF / 32, BB), dim3(32, 8)>>>(context, ctxThi, ctxTlo, CDF, SS);
    split_transpose_kernel<<<dim3(QQ / 32, IDF / 32, BB), dim3(32, 8)>>>(input, inThi, inTlo, IDF, QQ);

    // GEMM1: sourceT[b][i,s] = sum_c W[i,c] * ctxT[b][s,c]
    gemm_bf16x3<<<dim3(SS / 128, IDF / 128, BB), 256, GEMM_SMEM>>>(
        Whi, Wlo, ctxThi, ctxTlo, sourceT, CDF,
        0LL, (long long)SS * CDF, (long long)IDF * SS, SS);

    // Split sourceT (native for GEMM3-A, transposed for GEMM2-B)
    split_kernel<<<((long long)BB * IDF * SS / 4 + 255) / 256, 256>>>(
        sourceT, sThi, sTlo, (long long)BB * IDF * SS / 4);
    split_transpose_kernel<<<dim3(SS / 32, IDF / 32, BB), dim3(32, 8)>>>(sourceT, sTThi, sTTlo, IDF, SS);

    // GEMM2: attn[b][q,s] = sum_k inT[b][q,k] * sTT[b][s,k]
    gemm_bf16x3<<<dim3(SS / 128, QQ / 128, BB), 256, GEMM_SMEM>>>(
        inThi, inTlo, sTThi, sTTlo, attn, IDF,
        (long long)QQ * IDF, (long long)SS * IDF, (long long)QQ * SS, SS);

    // Softmax (in place) + emit attn hi/lo
    softmax_mask_kernel<<<BB * QQ, SS>>>(attn, mask, athi, atlo);

    // attn_out[b] = attn[b]^T
    transpose_qs_kernel<<<dim3(SS / 32, QQ / 32, BB), dim3(32, 8)>>>(attn, attn_out);

    // GEMM3: wc[b][i,q] = sum_s sT[b][i,s] * attn[b][q,s]
    gemm_bf16x3<<<dim3(QQ / 128, IDF / 128, BB), 256, GEMM_SMEM>>>(
        sThi, sTlo, athi, atlo, wc, SS,
        (long long)IDF * SS, (long long)QQ * SS, (long long)IDF * QQ, QQ);
}

// round 11
// speedup vs baseline: 2.0124x; 1.0007x over previous
#include <cuda_runtime.h>
#include <cuda_bf16.h>
#include <math.h>
#include <stdint.h>

// Problem constants
#define BB   32
#define IDF  1024
#define CDF  1024
#define QQ   2304     // 48*48
#define SS   256

// ---------------------------------------------------------------------------
// Device-global scratch (allocation-free per harness rules)
// ---------------------------------------------------------------------------
__device__ float g_sourceT[(size_t)BB * IDF * SS];                 // [B, IDF, S]
__device__ float g_attn   [(size_t)BB * QQ  * SS];                 // [B, Q, S]

__device__ __align__(16) __nv_bfloat16 g_Whi  [(size_t)IDF * CDF];
__device__ __align__(16) __nv_bfloat16 g_Wlo  [(size_t)IDF * CDF];
__device__ __align__(16) __nv_bfloat16 g_ctxThi[(size_t)BB * SS * CDF];   // [B][S, CDF]
__device__ __align__(16) __nv_bfloat16 g_ctxTlo[(size_t)BB * SS * CDF];
__device__ __align__(16) __nv_bfloat16 g_inThi [(size_t)BB * QQ * IDF];   // [B][Q, IDF]
__device__ __align__(16) __nv_bfloat16 g_inTlo [(size_t)BB * QQ * IDF];
__device__ __align__(16) __nv_bfloat16 g_sThi  [(size_t)BB * IDF * SS];   // [B][IDF, S]
__device__ __align__(16) __nv_bfloat16 g_sTlo  [(size_t)BB * IDF * SS];
__device__ __align__(16) __nv_bfloat16 g_sTThi [(size_t)BB * SS * IDF];   // [B][S, IDF]
__device__ __align__(16) __nv_bfloat16 g_sTTlo [(size_t)BB * SS * IDF];
__device__ __align__(16) __nv_bfloat16 g_attnhi[(size_t)BB * QQ * SS];    // [B][Q, S]
__device__ __align__(16) __nv_bfloat16 g_attnlo[(size_t)BB * QQ * SS];

// ---------------------------------------------------------------------------
// Helpers (plain sm_80-class instructions only: legal on target sm_103)
// ---------------------------------------------------------------------------
__device__ __forceinline__ uint32_t smem_u32(const void* p) {
    uint32_t a;
    asm("{ .reg .u64 t; cvta.to.shared.u64 t, %1; cvt.u32.u64 %0, t; }" : "=r"(a) : "l"(p));
    return a;
}
__device__ __forceinline__ void cp16(uint32_t s, const void* g) {
    asm volatile("cp.async.cg.shared.global [%0], [%1], 16;" :: "r"(s), "l"(g));
}
#define CP_COMMIT() asm volatile("cp.async.commit_group;" ::: "memory")
#define CP_WAIT(n)  asm volatile("cp.async.wait_group %0;" :: "n"(n) : "memory")

#define LDSM4(r, a) \
    asm volatile("ldmatrix.sync.aligned.m8n8.x4.shared.b16 {%0,%1,%2,%3}, [%4];" \
        : "=r"((r)[0]), "=r"((r)[1]), "=r"((r)[2]), "=r"((r)[3]) : "r"(a))

#define MMA_BF16(d, a, b0, b1) \
    asm volatile("mma.sync.aligned.m16n8k16.row.col.f32.bf16.bf16.f32 " \
        "{%0,%1,%2,%3}, {%4,%5,%6,%7}, {%8,%9}, {%0,%1,%2,%3};" \
        : "+f"((d)[0]), "+f"((d)[1]), "+f"((d)[2]), "+f"((d)[3]) \
        : "r"((a)[0]), "r"((a)[1]), "r"((a)[2]), "r"((a)[3]), "r"(b0), "r"(b1))

// ---------------------------------------------------------------------------
// bf16x3 split-precision batched GEMM (HMMA): D[m,n] = sum_k A[m,k]*B[n,k]
// A = Ahi+Alo [M,K] K-major, B = Bhi+Blo [N,K] K-major.
// Tile 128x128xBK32, 256 thr (8 warps, 4m x 2n), warp tile 32x64.
// Smem: 4 planes x 128 rows x 80B (64B data + 16B pad; row*80 mod 128 covers
// all eight 16B slots -> conflict-free ldmatrix), double buffered = 80 KB.
//
// Inner loop is organized in 3 PASSES (hi*hi, hi*lo, lo*hi) over all 16
// accumulators so each acc's 3 dependent MMAs are separated by 15 independent
// ones (R9 profile showed tensor=43.9% @ occ 12.5% from back-to-back RAW
// chains on the same accumulator).
// ---------------------------------------------------------------------------
#define PLANE_SZ 10240            // 128 * 80
#define STAGE_SZ 40960            // 4 planes
#define GEMM_SMEM (2 * STAGE_SZ)  // 81920

__global__ __launch_bounds__(256, 1)
void gemm_bf16x3(const __nv_bfloat16* __restrict__ Ahi, const __nv_bfloat16* __restrict__ Alo,
                 const __nv_bfloat16* __restrict__ Bhi, const __nv_bfloat16* __restrict__ Blo,
                 float* __restrict__ C, int K,
                 long long sA, long long sB, long long sC, int Ncols) {
    extern __shared__ __align__(128) char smem[];
    const uint32_t sbase = smem_u32(smem);
    const int tid = threadIdx.x, wid = tid >> 5, lane = tid & 31;
    const int m0 = blockIdx.y * 128;
    const int n0 = blockIdx.x * 128;
    const long long bz = blockIdx.z;
    Ahi += bz * sA; Alo += bz * sA;
    Bhi += bz * sB; Blo += bz * sB;
    C   += bz * sC;

    const __nv_bfloat16* pl[4] = {Ahi, Alo, Bhi, Blo};

    // Stage loader: 2048 16B chunks (4 planes x 128 rows x 4), 8 per thread.
    auto load_stage = [&](int kt, int st) {
        const uint32_t s0 = sbase + st * STAGE_SZ;
        const int k0 = kt * 32;
#pragma unroll
        for (int i = 0; i < 8; i++) {
            int ch = i * 256 + tid;
            int p  = ch >> 9;           // plane 0..3
            int rc = ch & 511;
            int r  = rc >> 2, c = rc & 3;
            int row = (p < 2 ? m0 : n0) + r;
            cp16(s0 + p * PLANE_SZ + r * 80 + c * 16,
                 pl[p] + (long long)row * K + k0 + c * 8);
        }
        CP_COMMIT();
    };

    const int wm = (wid & 3) * 32;   // warp m offset in tile
    const int wn = (wid >> 2) * 64;  // warp n offset in tile

    float acc[2][8][4];
#pragma unroll
    for (int mt = 0; mt < 2; mt++)
#pragma unroll
        for (int nt = 0; nt < 8; nt++)
#pragma unroll
            for (int e = 0; e < 4; e++) acc[mt][nt][e] = 0.f;

    const int KT = K / 32;
    load_stage(0, 0);

    for (int t = 0; t < KT; t++) {
        if (t + 1 < KT) { load_stage(t + 1, (t + 1) & 1); CP_WAIT(1); }
        else            { CP_WAIT(0); }
        __syncthreads();

        const uint32_t s0 = sbase + (t & 1) * STAGE_SZ;
#pragma unroll
        for (int ks = 0; ks < 2; ks++) {
            const uint32_t kb = ks * 32;  // k16 half in bytes

            // A fragments: lanes 0-15 -> rows @k0, 16-31 -> rows @k8
            uint32_t ah[2][4], al[2][4];
#pragma unroll
            for (int mt = 0; mt < 2; mt++) {
                uint32_t aaddr = s0 + (wm + mt * 16 + (lane & 15)) * 80 + kb + (lane >> 4) * 16;
                LDSM4(ah[mt], aaddr);
                LDSM4(al[mt], aaddr + PLANE_SZ);
            }
            // All B fragments for this k16 step (4 n16 groups x hi/lo)
            uint32_t bh[4][4], bl[4][4];
#pragma unroll
            for (int ng = 0; ng < 4; ng++) {
                uint32_t baddr = s0 + 2 * PLANE_SZ
                               + (wn + ng * 16 + (lane & 7) + (lane >> 4) * 8) * 80
                               + kb + ((lane >> 3) & 1) * 16;
                LDSM4(bh[ng], baddr);
                LDSM4(bl[ng], baddr + PLANE_SZ);
            }

            // Pass 1: hi*hi — 16 independent MMAs
#pragma unroll
            for (int mt = 0; mt < 2; mt++)
#pragma unroll
                for (int ng = 0; ng < 4; ng++) {
                    MMA_BF16(acc[mt][ng * 2],     ah[mt], bh[ng][0], bh[ng][1]);
                    MMA_BF16(acc[mt][ng * 2 + 1], ah[mt], bh[ng][2], bh[ng][3]);
                }
            // Pass 2: hi*lo
#pragma unroll
            for (int mt = 0; mt < 2; mt++)
#pragma unroll
                for (int ng = 0; ng < 4; ng++) {
                    MMA_BF16(acc[mt][ng * 2],     ah[mt], bl[ng][0], bl[ng][1]);
                    MMA_BF16(acc[mt][ng * 2 + 1], ah[mt], bl[ng][2], bl[ng][3]);
                }
            // Pass 3: lo*hi
#pragma unroll
            for (int mt = 0; mt < 2; mt++)
#pragma unroll
                for (int ng = 0; ng < 4; ng++) {
                    MMA_BF16(acc[mt][ng * 2],     al[mt], bh[ng][0], bh[ng][1]);
                    MMA_BF16(acc[mt][ng * 2 + 1], al[mt], bh[ng][2], bh[ng][3]);
                }
        }
        __syncthreads();
    }

    // Epilogue: fragment layout c0,c1 -> (g, 2j..2j+1); c2,c3 -> (g+8, ...)
    const int g = lane >> 2, j2 = (lane & 3) * 2;
#pragma unroll
    for (int mt = 0; mt < 2; mt++)
#pragma unroll
        for (int nt = 0; nt < 8; nt++) {
            long long row = m0 + wm + mt * 16 + g;
            long long col = n0 + wn + nt * 8 + j2;
            *(float2*)&C[row * Ncols + col]       = make_float2(acc[mt][nt][0], acc[mt][nt][1]);
            *(float2*)&C[(row + 8) * Ncols + col] = make_float2(acc[mt][nt][2], acc[mt][nt][3]);
        }
}

// ---------------------------------------------------------------------------
// Elementwise hi/lo split (flat, float4-vectorized)
// ---------------------------------------------------------------------------
__global__ void split_kernel(const float* __restrict__ src,
                             __nv_bfloat16* __restrict__ hi,
                             __nv_bfloat16* __restrict__ lo, long long n4) {
    long long i = (long long)blockIdx.x * blockDim.x + threadIdx.x;
    if (i >= n4) return;
    float4 v = ((const float4*)src)[i];
    float a[4] = {v.x, v.y, v.z, v.w};
    __nv_bfloat16 h[4], l[4];
#pragma unroll
    for (int k = 0; k < 4; k++) {
        h[k] = __float2bfloat16(a[k]);
        l[k] = __float2bfloat16(a[k] - __bfloat162float(h[k]));
    }
    ((__nv_bfloat162*)hi)[2 * i]     = __nv_bfloat162(h[0], h[1]);
    ((__nv_bfloat162*)hi)[2 * i + 1] = __nv_bfloat162(h[2], h[3]);
    ((__nv_bfloat162*)lo)[2 * i]     = __nv_bfloat162(l[0], l[1]);
    ((__nv_bfloat162*)lo)[2 * i + 1] = __nv_bfloat162(l[2], l[3]);
}

// ---------------------------------------------------------------------------
// Split + transpose: src [b][R,C] fp32 -> hiT/loT [b][C,R] bf16
// grid (C/32, R/32, B), block (32, 8)
// ---------------------------------------------------------------------------
__global__ void split_transpose_kernel(const float* __restrict__ src,
                                       __nv_bfloat16* __restrict__ hiT,
                                       __nv_bfloat16* __restrict__ loT,
                                       int R, int C) {
    __shared__ float tile[32][33];
    const long long base = (long long)blockIdx.z * R * C;
    const int c0 = blockIdx.x * 32, r0 = blockIdx.y * 32;
    const int x = threadIdx.x, y = threadIdx.y;
    const float* s = src + base;
#pragma unroll
    for (int i = 0; i < 32; i += 8)
        tile[y + i][x] = s[(long long)(r0 + y + i) * C + c0 + x];
    __syncthreads();
#pragma unroll
    for (int i = 0; i < 32; i += 8) {
        float v = tile[x][y + i];
        __nv_bfloat16 h = __float2bfloat16(v);
        long long o = base + (long long)(c0 + y + i) * R + r0 + x;
        hiT[o] = h;
        loT[o] = __float2bfloat16(v - __bfloat162float(h));
    }
}

// ---------------------------------------------------------------------------
// Masked softmax over S=256 (in place) + emit hi/lo bf16 planes.
// Row (b*Q+q) uses mask[q % 32] (faithful to reference tiling; Q % B == 0).
// Mask: harness 4-byte encoding; nonzero word == masked (int32 or fp32).
// ---------------------------------------------------------------------------
__global__ void softmax_mask_kernel(float* __restrict__ attn,
                                    const unsigned int* __restrict__ mask,
                                    __nv_bfloat16* __restrict__ ahi,
                                    __nv_bfloat16* __restrict__ alo) {
    const long long row = blockIdx.x;
    const int q = (int)(row % QQ);
    const int s = threadIdx.x;

    float v = attn[row * SS + s];
    if (mask[(q & (BB - 1)) * SS + s] != 0u) v = -1e30f;

    __shared__ float red[8];
    float m = v;
#pragma unroll
    for (int o = 16; o > 0; o >>= 1) m = fmaxf(m, __shfl_xor_sync(0xffffffffu, m, o));
    if ((s & 31) == 0) red[s >> 5] = m;
    __syncthreads();
    float mx = red[0];
#pragma unroll
    for (int i = 1; i < 8; i++) mx = fmaxf(mx, red[i]);
    __syncthreads();

    float e = __expf(v - mx);
    float t = e;
#pragma unroll
    for (int o = 16; o > 0; o >>= 1) t += __shfl_xor_sync(0xffffffffu, t, o);
    if ((s & 31) == 0) red[s >> 5] = t;
    __syncthreads();
    float sum = 0.f;
#pragma unroll
    for (int i = 0; i < 8; i++) sum += red[i];

    float p = e / sum;
    attn[row * SS + s] = p;
    __nv_bfloat16 h = __float2bfloat16(p);
    ahi[row * SS + s] = h;
    alo[row * SS + s] = __float2bfloat16(p - __bfloat162float(h));
}

// ---------------------------------------------------------------------------
// Transpose per-batch [Q, S] -> [S, Q] into attn_out
// ---------------------------------------------------------------------------
__global__ void transpose_qs_kernel(const float* __restrict__ attn,
                                    float* __restrict__ out) {
    __shared__ float tile[32][33];
    const int b  = blockIdx.z;
    const int s0 = blockIdx.x * 32;
    const int q0 = blockIdx.y * 32;
    const float* src = attn + (long long)b * QQ * SS;
    float*       dst = out  + (long long)b * SS * QQ;
    const int x = threadIdx.x, y = threadIdx.y;
#pragma unroll
    for (int i = 0; i < 32; i += 8)
        tile[y + i][x] = src[(long long)(q0 + y + i) * SS + s0 + x];
    __syncthreads();
#pragma unroll
    for (int i = 0; i < 32; i += 8)
        dst[(long long)(s0 + y + i) * QQ + q0 + x] = tile[x][y + i];
}

// ---------------------------------------------------------------------------
// Launch
// ---------------------------------------------------------------------------
extern "C" void kernel_launch(void* const* d_in, const int* in_sizes, int n_in,
                              void* d_out, int out_size) {
    const float*        input   = (const float*)d_in[0];          // [B, IDF, 48, 48]
    const float*        context = (const float*)d_in[1];          // [B, CDF, S]
    const unsigned int* mask    = (const unsigned int*)d_in[2];   // [B, S]
    const float*        W       = (const float*)d_in[3];          // [IDF, CDF]

    float* out      = (float*)d_out;
    float* wc       = out;                                  // [B, IDF, Q]
    float* attn_out = out + (size_t)BB * IDF * QQ;          // [B, S, Q]

    float *sourceT, *attn;
    __nv_bfloat16 *Whi, *Wlo, *ctxThi, *ctxTlo, *inThi, *inTlo;
    __nv_bfloat16 *sThi, *sTlo, *sTThi, *sTTlo, *athi, *atlo;
    cudaGetSymbolAddress((void**)&sourceT, g_sourceT);
    cudaGetSymbolAddress((void**)&attn,    g_attn);
    cudaGetSymbolAddress((void**)&Whi,     g_Whi);
    cudaGetSymbolAddress((void**)&Wlo,     g_Wlo);
    cudaGetSymbolAddress((void**)&ctxThi,  g_ctxThi);
    cudaGetSymbolAddress((void**)&ctxTlo,  g_ctxTlo);
    cudaGetSymbolAddress((void**)&inThi,   g_inThi);
    cudaGetSymbolAddress((void**)&inTlo,   g_inTlo);
    cudaGetSymbolAddress((void**)&sThi,    g_sThi);
    cudaGetSymbolAddress((void**)&sTlo,    g_sTlo);
    cudaGetSymbolAddress((void**)&sTThi,   g_sTThi);
    cudaGetSymbolAddress((void**)&sTTlo,   g_sTTlo);
    cudaGetSymbolAddress((void**)&athi,    g_attnhi);
    cudaGetSymbolAddress((void**)&atlo,    g_attnlo);

    cudaFuncSetAttribute(gemm_bf16x3, cudaFuncAttributeMaxDynamicSharedMemorySize, GEMM_SMEM);

    // Stage bf16 hi/lo planes
    split_kernel<<<(IDF * CDF / 4 + 255) / 256, 256>>>(W, Whi, Wlo, (long long)IDF * CDF / 4);
    split_transpose_kernel<<<dim3(SS / 32, CDF / 32, BB), dim3(32, 8)>>>(context, ctxThi, ctxTlo, CDF, SS);
    split_transpose_kernel<<<dim3(QQ / 32, IDF / 32, BB), dim3(32, 8)>>>(input, inThi, inTlo, IDF, QQ);

    // GEMM1: sourceT[b][i,s] = sum_c W[i,c] * ctxT[b][s,c]
    gemm_bf16x3<<<dim3(SS / 128, IDF / 128, BB), 256, GEMM_SMEM>>>(
        Whi, Wlo, ctxThi, ctxTlo, sourceT, CDF,
        0LL, (long long)SS * CDF, (long long)IDF * SS, SS);

    // Split sourceT (native for GEMM3-A, transposed for GEMM2-B)
    split_kernel<<<((long long)BB * IDF * SS / 4 + 255) / 256, 256>>>(
        sourceT, sThi, sTlo, (long long)BB * IDF * SS / 4);
    split_transpose_kernel<<<dim3(SS / 32, IDF / 32, BB), dim3(32, 8)>>>(sourceT, sTThi, sTTlo, IDF, SS);

    // GEMM2: attn[b][q,s] = sum_k inT[b][q,k] * sTT[b][s,k]
    gemm_bf16x3<<<dim3(SS / 128, QQ / 128, BB), 256, GEMM_SMEM>>>(
        inThi, inTlo, sTThi, sTTlo, attn, IDF,
        (long long)QQ * IDF, (long long)SS * IDF, (long long)QQ * SS, SS);

    // Softmax (in place) + emit attn hi/lo
    softmax_mask_kernel<<<BB * QQ, SS>>>(attn, mask, athi, atlo);

    // attn_out[b] = attn[b]^T
    transpose_qs_kernel<<<dim3(SS / 32, QQ / 32, BB), dim3(32, 8)>>>(attn, attn_out);

    // GEMM3: wc[b][i,q] = sum_s sT[b][i,s] * attn[b][q,s]
    gemm_bf16x3<<<dim3(QQ / 128, IDF / 128, BB), 256, GEMM_SMEM>>>(
        sThi, sTlo, athi, atlo, wc, SS,
        (long long)IDF * SS, (long long)QQ * SS, (long long)IDF * QQ, QQ);
}